// round 17
// baseline (speedup 1.0000x reference)
#include <cuda_runtime.h>

// noiseRNN: h_t = tanh(W_ih x_t + b_ih + W_hh h_{t-1} + b_hh); carry h_t + 0.1*noise_t
// T=2048, B=256, I=64, H=128.
// R17: STRUCTURALLY ENFORCED ANTI-PHASE between the two per-batch groups.
// 128 blocks x 256 threads; group g = tid>>7 owns batch 2*blockIdx.x+g
// (4 warps, thread = 4 j-rows x 48 k in regs, 12 warp-uniform LDS.128,
// 4-partial SMEM reduce, depth-4 prefetch rings, fast tanh).
// Two CTA-wide named barriers A(id1)/B(id2) are hit at COMPLEMENTARY points:
//   g0: mv(t) A rd(t) B ...          g1: A(boot) mv(t) B rd(t) A ...
// so every barrier pairs one group's post-matvec with the other's post-reduce:
// each half-step = {one group's solo full-issue matvec || other group's
// latency tail}. Locked anti-phase; barrier counts balanced with one trailing
// A arrival from g0 (A: 2049/2049, B: 2048/2048 -> no deadlock).

#define T_STEPS 2048
#define BATCH   256
#define IN_DIM  64
#define HID     128
#define KDIM    192           // HID + IN_DIM
#define STD_F   0.1f
#define THREADS 256
#define NP      4             // prefetch ring depth (T_STEPS % NP == 0)

__device__ __forceinline__ unsigned long long fma2(unsigned long long a,
                                                   unsigned long long b,
                                                   unsigned long long c) {
    unsigned long long d;
    asm("fma.rn.f32x2 %0, %1, %2, %3;" : "=l"(d) : "l"(a), "l"(b), "l"(c));
    return d;
}
__device__ __forceinline__ unsigned long long packf2(float lo, float hi) {
    return (unsigned long long)__float_as_uint(lo) |
           ((unsigned long long)__float_as_uint(hi) << 32);
}
__device__ __forceinline__ float lo_f(unsigned long long v) {
    return __uint_as_float((unsigned)v);
}
__device__ __forceinline__ float hi_f(unsigned long long v) {
    return __uint_as_float((unsigned)(v >> 32));
}
// tanh(s) = 1 - 2/(exp(2s)+1): 2 MUFU + few fp ops, ~1e-6 accuracy (validated).
__device__ __forceinline__ float fast_tanh(float s) {
    float e = __expf(2.0f * s);
    return 1.0f - __fdividef(2.0f, e + 1.0f);
}
// CTA-wide named barrier (both groups arrive, possibly at different PCs)
__device__ __forceinline__ void bar_named(int id) {
    asm volatile("bar.sync %0, %1;" :: "r"(id), "r"(THREADS) : "memory");
}

__global__ void __launch_bounds__(THREADS, 1) noise_rnn_kernel(
    const float* __restrict__ x,         // [T,B,I]
    const float* __restrict__ w_ih,      // [H,I]
    const float* __restrict__ w_hh,      // [H,H]
    const float* __restrict__ b_ih,      // [H]
    const float* __restrict__ b_hh,      // [H]
    const float* __restrict__ noise,     // [T,B,H]
    const float* __restrict__ hidden_in, // [1,B,H]
    float* __restrict__ out,             // [T,B,H] (+ [1,B,H] h_last)
    int out_size)
{
    __shared__ __align__(16) float zsh[2][KDIM];        // per-group z = [h; x_t]
    __shared__ __align__(16) float psh[2][4 * HID];     // per-group partials

    const int tid  = threadIdx.x;
    const int lane = tid & 31;
    const int gid  = tid >> 7;          // group 0/1
    const int gtid = tid & 127;         // thread id within group
    const int wg   = gtid >> 5;         // warp within group (0..3)
    const int b    = blockIdx.x * 2 + gid;   // this group's batch

    const int jbase = lane * 4;         // matvec: this thread's 4 output rows
    const int ks    = wg * 48;          // k-slice start (48 wide)
    const int rj    = gtid;             // reduce: this thread's output row

    float* const z  = zsh[gid];
    float* const ps = psh[gid];

    // barrier ids from this group's perspective:
    // first bar after matvec, second bar after reduce
    const int barMv = (gid == 0) ? 1 : 2;
    const int barRd = (gid == 0) ? 2 : 1;

    // --- W_cat tile in registers, k-pair packed ---
    // W_cat[j][k] = k < HID ? w_hh[j][k] : w_ih[j][k-HID]
    unsigned long long wpk[4][24];
#pragma unroll
    for (int p = 0; p < 24; ++p) {
        const int k0 = ks + 2 * p;
        const int k1 = k0 + 1;
#pragma unroll
        for (int jj = 0; jj < 4; ++jj) {
            const int j = jbase + jj;
            const float lo = (k0 < HID) ? w_hh[j * HID + k0]
                                        : w_ih[j * IN_DIM + (k0 - HID)];
            const float hi = (k1 < HID) ? w_hh[j * HID + k1]
                                        : w_ih[j * IN_DIM + (k1 - HID)];
            wpk[jj][p] = packf2(lo, hi);
        }
    }

    const float bias_r = b_ih[rj] + b_hh[rj];
    const bool  stX    = (rj < IN_DIM);     // this thread also stages x[rj]

    // --- init z(t=0) = [h0; x0] ---
    z[rj] = hidden_in[b * HID + rj];
    if (stX) z[HID + rj] = x[b * IN_DIM + rj];
    __syncthreads();

    const int nb = b * HID + rj;        // out/noise offset
    const int xg = b * IN_DIM + rj;     // x offset (stX threads)

    // --- depth-NP prefetch rings ---
    float nzr[NP], xr[NP];
#pragma unroll
    for (int u = 0; u < NP; ++u) {
        nzr[u] = noise[u * (BATCH * HID) + nb];
        xr[u]  = (stX && (u + 1) < T_STEPS)
                 ? x[(u + 1) * (BATCH * IN_DIM) + xg] : 0.0f;
    }

    // --- bootstrap: g1 arrives at barrier id1 once so instance pairing is
    //     g0 post-mv <-> g1 post-rd (and vice versa) for the whole run ---
    if (gid == 1) bar_named(1);

    for (int t = 0; t < T_STEPS; t += NP) {
#pragma unroll
        for (int u = 0; u < NP; ++u) {
            const int tt = t + u;

            const float nz = nzr[u];
            const float xn = xr[u];
            if ((tt + NP) < T_STEPS)
                nzr[u] = noise[(tt + NP) * (BATCH * HID) + nb];
            if (stX && (tt + NP + 1) < T_STEPS)
                xr[u] = x[(tt + NP + 1) * (BATCH * IN_DIM) + xg];

            // --- matvec partials: 4 j-rows x 48 k (12 LDS.128, 96 fma2) ---
            unsigned long long a0 = 0ull, a1 = 0ull, a2 = 0ull, a3 = 0ull;
            const ulonglong2* zq = reinterpret_cast<const ulonglong2*>(z + ks);
#pragma unroll
            for (int q = 0; q < 12; ++q) {
                const ulonglong2 v = zq[q];   // warp-uniform broadcast LDS.128
                a0 = fma2(wpk[0][2 * q], v.x, a0); a0 = fma2(wpk[0][2 * q + 1], v.y, a0);
                a1 = fma2(wpk[1][2 * q], v.x, a1); a1 = fma2(wpk[1][2 * q + 1], v.y, a1);
                a2 = fma2(wpk[2][2 * q], v.x, a2); a2 = fma2(wpk[2][2 * q + 1], v.y, a2);
                a3 = fma2(wpk[3][2 * q], v.x, a3); a3 = fma2(wpk[3][2 * q + 1], v.y, a3);
            }
            {
                float4 p;
                p.x = lo_f(a0) + hi_f(a0);
                p.y = lo_f(a1) + hi_f(a1);
                p.z = lo_f(a2) + hi_f(a2);
                p.w = lo_f(a3) + hi_f(a3);
                *reinterpret_cast<float4*>(ps + wg * HID + jbase) = p;
            }
            bar_named(barMv);   // pairs with other group's post-reduce arrival

            // --- reduce: thread rj owns output row rj (4 partials, depth-2 tree) ---
            const float q0 = ps[0 * HID + rj];
            const float q1 = ps[1 * HID + rj];
            const float q2 = ps[2 * HID + rj];
            const float q3 = ps[3 * HID + rj];
            const float s  = ((q0 + q1) + (q2 + q3)) + bias_r;

            const float hn = fast_tanh(s);
            out[tt * (BATCH * HID) + nb] = hn;

            const float zn = hn + STD_F * nz;    // noisy carried state
            z[rj] = zn;
            if (stX && (tt + 1) < T_STEPS)
                z[HID + rj] = xn;                // stage next x

            if (tt == T_STEPS - 1 && out_size > T_STEPS * BATCH * HID)
                out[T_STEPS * (BATCH * HID) + nb] = zn;   // h_last

            bar_named(barRd);   // pairs with other group's post-matvec arrival
        }
    }

    // --- balance barrier id1 counts (g1 arrived once extra at bootstrap) ---
    if (gid == 0) bar_named(1);
}

extern "C" void kernel_launch(void* const* d_in, const int* in_sizes, int n_in,
                              void* d_out, int out_size) {
    const float* x         = (const float*)d_in[0];
    const float* w_ih      = (const float*)d_in[1];
    const float* w_hh      = (const float*)d_in[2];
    const float* b_ih      = (const float*)d_in[3];
    const float* b_hh      = (const float*)d_in[4];
    const float* noise     = (const float*)d_in[5];
    const float* hidden_in = (const float*)d_in[6];
    float* out = (float*)d_out;

    noise_rnn_kernel<<<BATCH / 2, THREADS>>>(x, w_ih, w_hh, b_ih, b_hh,
                                             noise, hidden_in, out, out_size);
}